// round 14
// baseline (speedup 1.0000x reference)
#include <cuda_runtime.h>
#include <cuda_bf16.h>
#include <math.h>
#include <cstdint>

#define NHH 12
#define DKK 64
#define DVV 128
#define BB  4
#define LL  2048
#define HH  1024
#define KD  768
#define VD  1536
#define BL  (BB*LL)
#define NTOT 4608

typedef unsigned long long u64;
typedef unsigned int u32;

#define FMA2(c, a, b) asm("fma.rn.f32x2 %0, %1, %2, %0;" : "+l"(c) : "l"(a), "l"(b))
#define MUL2(d, a, b) asm("mul.rn.f32x2 %0, %1, %2;" : "=l"(d) : "l"(a), "l"(b))
#define DUP2(d, s)    asm("mov.b64 %0, {%1, %1};" : "=l"(d) : "r"(s))
#define UNPK2(lo, hi, v) asm("mov.b64 {%0, %1}, %2;" : "=r"(lo), "=r"(hi) : "l"(v))

__device__ __forceinline__ uint32_t smem_to_u32(const void* p) {
    uint32_t a;
    asm("{ .reg .u64 t; cvta.to.shared.u64 t, %1; cvt.u32.u64 %0, t; }" : "=r"(a) : "l"(p));
    return a;
}

#define LDSM4(r0, r1, r2, r3, addr) \
    asm volatile("ldmatrix.sync.aligned.m8n8.x4.shared.b16 {%0,%1,%2,%3}, [%4];" \
        : "=r"(r0), "=r"(r1), "=r"(r2), "=r"(r3) : "r"(addr))

#define MMA16816(c, a, b0, b1) \
    asm volatile("mma.sync.aligned.m16n8k16.row.col.f32.bf16.bf16.f32 " \
        "{%0,%1,%2,%3},{%4,%5,%6,%7},{%8,%9},{%0,%1,%2,%3};" \
        : "+f"((c)[0]), "+f"((c)[1]), "+f"((c)[2]), "+f"((c)[3]) \
        : "r"((a)[0]), "r"((a)[1]), "r"((a)[2]), "r"((a)[3]), "r"(b0), "r"(b1))

__device__ __forceinline__ void cpa16(uint32_t saddr, const void* g) {
    asm volatile("cp.async.cg.shared.global [%0], [%1], 16;" :: "r"(saddr), "l"(g));
}
#define CP_COMMIT() asm volatile("cp.async.commit_group;" ::: "memory")
#define CP_WAIT0()  asm volatile("cp.async.wait_group 0;" ::: "memory")

// ================= scratch =================
__device__ float g_qkvg[(size_t)BL * NTOT];
__device__ __nv_bfloat16 g_hsh[(size_t)BL * HH], g_hsl[(size_t)BL * HH];
__device__ __nv_bfloat16 g_wth[(size_t)NTOT * HH], g_wtl[(size_t)NTOT * HH];
__device__ __nv_bfloat16 g_woth[(size_t)HH * VD], g_wotl[(size_t)HH * VD];
__device__ __nv_bfloat16 g_oh[(size_t)BL * VD], g_ol[(size_t)BL * VD];
__device__ float g_bufQc[BL*KD], g_bufKc[BL*KD], g_bufVc[BL*VD], g_bufO[BL*VD];
__device__ float g_gk[BL*NHH], g_beta[BL*NHH];

// ================= hi/lo split =================
__global__ void split_kernel(const float* __restrict__ in,
                             __nv_bfloat16* __restrict__ oh, __nv_bfloat16* __restrict__ ol, int n) {
    int i = blockIdx.x * 256 + threadIdx.x;
    if (i >= n) return;
    float x = in[i];
    __nv_bfloat16 h = __float2bfloat16(x);
    oh[i] = h;
    ol[i] = __float2bfloat16(x - __bfloat162float(h));
}

// ================= fused transpose+split of all 5 weight matrices =================
__device__ __forceinline__ void transp_tile(const float* __restrict__ W, int K, int N,
                                            __nv_bfloat16* __restrict__ Th,
                                            __nv_bfloat16* __restrict__ Tl,
                                            int n0, int k0, float* tile) {
    int tx = threadIdx.x, ty = threadIdx.y;
    for (int i = ty; i < 32; i += 8)
        tile[i * 33 + tx] = W[(size_t)(k0 + i) * N + n0 + tx];
    __syncthreads();
    for (int i = ty; i < 32; i += 8) {
        float x = tile[tx * 33 + i];
        __nv_bfloat16 h = __float2bfloat16(x);
        size_t o = (size_t)(n0 + i) * K + k0 + tx;
        Th[o] = h;
        Tl[o] = __float2bfloat16(x - __bfloat162float(h));
    }
}

__global__ void transp_all(const float* __restrict__ Wq, const float* __restrict__ Wk,
                           const float* __restrict__ Wv, const float* __restrict__ Wg,
                           const float* __restrict__ Wo,
                           __nv_bfloat16* __restrict__ wth, __nv_bfloat16* __restrict__ wtl,
                           __nv_bfloat16* __restrict__ woth, __nv_bfloat16* __restrict__ wotl) {
    __shared__ float tile[32 * 33];
    int idx = blockIdx.x;
    if (idx < 768) {
        transp_tile(Wq, HH, KD, wth, wtl, (idx % 24) * 32, (idx / 24) * 32, tile);
    } else if (idx < 1536) {
        idx -= 768;
        transp_tile(Wk, HH, KD, wth + (size_t)768 * HH, wtl + (size_t)768 * HH,
                    (idx % 24) * 32, (idx / 24) * 32, tile);
    } else if (idx < 3072) {
        idx -= 1536;
        transp_tile(Wv, HH, VD, wth + (size_t)1536 * HH, wtl + (size_t)1536 * HH,
                    (idx % 48) * 32, (idx / 48) * 32, tile);
    } else if (idx < 4608) {
        idx -= 3072;
        transp_tile(Wg, HH, VD, wth + (size_t)3072 * HH, wtl + (size_t)3072 * HH,
                    (idx % 48) * 32, (idx / 48) * 32, tile);
    } else {
        idx -= 4608;
        transp_tile(Wo, VD, HH, woth, wotl, (idx % 32) * 32, (idx / 32) * 32, tile);
    }
}

// ================= mma.sync split-bf16 GEMM (128x128, 2 CTA/SM) =================
#define TILE_B 10240
#define SMEM_GEMM (8 * TILE_B)

__global__ void __launch_bounds__(256, 2)
gemm_mma(const __nv_bfloat16* __restrict__ Ahi, const __nv_bfloat16* __restrict__ Alo,
         const __nv_bfloat16* __restrict__ Bhi, const __nv_bfloat16* __restrict__ Blo,
         float* __restrict__ C, int Kdim, int ldc) {
    extern __shared__ char smem[];
    const uint32_t smb = smem_to_u32(smem);
    const int tid = threadIdx.x;
    const int lane = tid & 31, w = tid >> 5;
    const int wm = (w & 1) * 64, wn = (w >> 1) * 32;
    const int m0 = blockIdx.y * 128, n0 = blockIdx.x * 128;

    const int rL = tid >> 1;
    const int qL = (tid & 1) * 2;

    float c[4][4][4];
#pragma unroll
    for (int i = 0; i < 4; i++)
#pragma unroll
        for (int j = 0; j < 4; j++)
#pragma unroll
            for (int e = 0; e < 4; e++) c[i][j][e] = 0.f;

    const int nCh = Kdim >> 5;

    auto load_stage = [&](int kc, int st) {
        const __nv_bfloat16* a0 = Ahi + (size_t)(m0 + rL) * Kdim + kc * 32 + qL * 8;
        const __nv_bfloat16* a1 = Alo + (size_t)(m0 + rL) * Kdim + kc * 32 + qL * 8;
        const __nv_bfloat16* b0 = Bhi + (size_t)(n0 + rL) * Kdim + kc * 32 + qL * 8;
        const __nv_bfloat16* b1 = Blo + (size_t)(n0 + rL) * Kdim + kc * 32 + qL * 8;
        uint32_t sa0 = smb + (st * 2 + 0) * TILE_B + rL * 80 + qL * 16;
        uint32_t sa1 = smb + (st * 2 + 1) * TILE_B + rL * 80 + qL * 16;
        uint32_t sb0 = smb + 4 * TILE_B + (st * 2 + 0) * TILE_B + rL * 80 + qL * 16;
        uint32_t sb1 = smb + 4 * TILE_B + (st * 2 + 1) * TILE_B + rL * 80 + qL * 16;
        cpa16(sa0, a0); cpa16(sa0 + 16, a0 + 8);
        cpa16(sa1, a1); cpa16(sa1 + 16, a1 + 8);
        cpa16(sb0, b0); cpa16(sb0 + 16, b0 + 8);
        cpa16(sb1, b1); cpa16(sb1 + 16, b1 + 8);
        CP_COMMIT();
    };

    load_stage(0, 0);

    for (int kc = 0; kc < nCh; kc++) {
        const int st = kc & 1;
        CP_WAIT0();
        __syncthreads();
        if (kc + 1 < nCh) load_stage(kc + 1, st ^ 1);

        const int lrow = lane & 15;
        const int lcolB = ((lane >> 4) << 3) * 2;
#pragma unroll
        for (int ks = 0; ks < 2; ks++) {
            const int kbB = ks * 32 + lcolB;
            uint32_t bh[2][4], bl[2][4];
#pragma unroll
            for (int np = 0; np < 2; np++) {
                int row = wn + np * 16 + lrow;
                uint32_t bd = smb + 4 * TILE_B + st * 2 * TILE_B + row * 80 + kbB;
                LDSM4(bh[np][0], bh[np][1], bh[np][2], bh[np][3], bd);
                LDSM4(bl[np][0], bl[np][1], bl[np][2], bl[np][3], bd + TILE_B);
            }
#pragma unroll
            for (int mt = 0; mt < 4; mt++) {
                uint32_t ah[4], al[4];
                int row = wm + mt * 16 + lrow;
                uint32_t ad = smb + st * 2 * TILE_B + row * 80 + kbB;
                LDSM4(ah[0], ah[1], ah[2], ah[3], ad);
                LDSM4(al[0], al[1], al[2], al[3], ad + TILE_B);
#pragma unroll
                for (int nt = 0; nt < 4; nt++) {
                    int np = nt >> 1, s = nt & 1;
                    MMA16816(c[mt][nt], ah, bh[np][s], bh[np][s + 2]);
                    MMA16816(c[mt][nt], ah, bl[np][s], bl[np][s + 2]);
                    MMA16816(c[mt][nt], al, bh[np][s], bh[np][s + 2]);
                }
            }
        }
    }
    CP_WAIT0();

#pragma unroll
    for (int mt = 0; mt < 4; mt++) {
        int row = m0 + wm + mt * 16 + (lane >> 2);
#pragma unroll
        for (int nt = 0; nt < 4; nt++) {
            int col = n0 + wn + nt * 8 + (lane & 3) * 2;
            *(float2*)(C + (size_t)row * ldc + col)       = make_float2(c[mt][nt][0], c[mt][nt][1]);
            *(float2*)(C + (size_t)(row + 8) * ldc + col) = make_float2(c[mt][nt][2], c[mt][nt][3]);
        }
    }
}

// ================= gk / beta projection =================
__global__ void gkbeta2(const float* __restrict__ hs,
                        const float* __restrict__ Wgk, const float* __restrict__ Wb,
                        const float* __restrict__ bb,  const float* __restrict__ A_log,
                        const float* __restrict__ dt_bias,
                        float* __restrict__ gk, float* __restrict__ beta) {
    __shared__ float sh[8][HH];
    int w = threadIdx.x >> 5, lane = threadIdx.x & 31;
    int row = blockIdx.x * 8 + w;
    const float* hr = hs + (size_t)row * HH;
    for (int i = lane; i < HH; i += 32) sh[w][i] = hr[i];
    __syncwarp();
    if (lane < 24) {
        const float* W = (lane < 12) ? Wgk : Wb;
        int j = (lane < 12) ? lane : lane - 12;
        float acc = 0.f;
#pragma unroll 4
        for (int k = 0; k < HH; k++) acc += sh[w][k] * W[k * NHH + j];
        if (lane < 12) {
            acc += dt_bias[j];
            float sp = (acc > 20.f) ? acc : log1pf(expf(acc));
            gk[row * NHH + j] = -expf(A_log[j]) * sp;
        } else {
            acc += bb[j];
            beta[row * NHH + j] = 1.f / (1.f + expf(-acc));
        }
    }
}

// ================= conv + silu + l2norm (q & k, 4 units per 256-thr CTA) =================
__global__ void __launch_bounds__(256)
conv_silu_l2qk(const float* __restrict__ qkvg,
               const float* __restrict__ wq, const float* __restrict__ wk,
               float* __restrict__ outq, float* __restrict__ outk) {
    __shared__ float sred[8];
    int tid  = threadIdx.x;
    int unit = tid >> 6;         // 0..3
    int ch   = tid & 63;
    int idx  = blockIdx.x * 4 + unit;
    int which = idx & 1;
    idx >>= 1;
    int h  = idx % NHH;
    int bl = idx / NHH;
    int l  = bl % LL;
    int c  = h * DKK + ch;
    const float* in = qkvg + (which ? 768 : 0);
    const float* wr = (which ? wk : wq) + c * 4;
    float* out = which ? outk : outq;
    float acc = 0.f;
#pragma unroll
    for (int j = 0; j < 4; j++) {
        int tt = l - 3 + j;
        if (tt >= 0) acc += in[(size_t)(bl - l + tt) * NTOT + c] * wr[j];
    }
    float sv = acc / (1.f + expf(-acc));
    float ss = sv * sv;
#pragma unroll
    for (int off = 16; off; off >>= 1) ss += __shfl_xor_sync(0xffffffffu, ss, off);
    if ((tid & 31) == 0) sred[tid >> 5] = ss;
    __syncthreads();
    float n = sqrtf(sred[unit * 2] + sred[unit * 2 + 1]);
    out[(size_t)bl * KD + c] = sv / fmaxf(n, 1e-12f);
}

__global__ void conv_silu_v(const float* __restrict__ in, int istride,
                            const float* __restrict__ w, float* __restrict__ out, int total) {
    int gid = blockIdx.x * blockDim.x + threadIdx.x;
    if (gid >= total) return;
    int c  = gid % VD;
    int bl = gid / VD;
    int l  = bl % LL;
    const float* wr = w + c * 4;
    float acc = 0.f;
#pragma unroll
    for (int j = 0; j < 4; j++) {
        int tt = l - 3 + j;
        if (tt >= 0) acc += in[(size_t)(bl - l + tt) * istride + c] * wr[j];
    }
    out[gid] = acc / (1.f + expf(-acc));
}

// ================= recurrence v5: 128 thr, 16-step groups (best known) =================
#define TS 16
__global__ void __launch_bounds__(128)
recur5(const float* __restrict__ q, const float* __restrict__ k,
       const float* __restrict__ v, const float* __restrict__ gk,
       const float* __restrict__ beta, float* __restrict__ o) {
    int blk = blockIdx.x;
    int b  = blk / (NHH * 2);
    int h  = (blk >> 1) % NHH;
    int vh = blk & 1;
    int tid = threadIdx.x;
    int col  = tid >> 1;
    int half = tid & 1;

    __shared__ float ksh[2][TS][64];
    __shared__ float qsh[2][TS][64];
    __shared__ float vsh[2][TS][64];
    __shared__ float egsh[LL];
    __shared__ float bsh[LL];

    const float* qb = q + (size_t)b * LL * KD + h * DKK;
    const float* kb = k + (size_t)b * LL * KD + h * DKK;
    const float* vb = v + (size_t)b * LL * VD + h * DVV + vh * 64;
    const float* gb = gk + (size_t)b * LL * NHH + h;
    const float* be = beta + (size_t)b * LL * NHH + h;
    float* ob = o + (size_t)b * LL * VD + h * DVV + vh * 64;

    for (int i = tid; i < LL; i += 128) {
        egsh[i] = expf(gb[(size_t)i * NHH]);
        bsh[i]  = be[(size_t)i * NHH];
    }

    u64 S2[16];
#pragma unroll
    for (int i = 0; i < 16; i++) S2[i] = 0ull;

    const int ls = tid >> 6;
    const int lc = tid & 63;
#pragma unroll
    for (int i = 0; i < TS / 2; i++) {
        int s = i * 2 + ls;
        ksh[0][s][lc] = kb[(size_t)s * KD + lc];
        qsh[0][s][lc] = qb[(size_t)s * KD + lc];
        vsh[0][s][lc] = vb[(size_t)s * VD + lc];
    }
    __syncthreads();

    const int NG = LL / TS;
    for (int g = 0; g < NG; g++) {
        const int buf = g & 1;
        float rk[TS / 2], rq[TS / 2], rv[TS / 2];
        const bool more = (g + 1) < NG;
        if (more) {
            int t0 = (g + 1) * TS;
#pragma unroll
            for (int i = 0; i < TS / 2; i++) {
                int s = i * 2 + ls;
                rk[i] = kb[(size_t)(t0 + s) * KD + lc];
                rq[i] = qb[(size_t)(t0 + s) * KD + lc];
                rv[i] = vb[(size_t)(t0 + s) * VD + lc];
            }
        }
#pragma unroll
        for (int s = 0; s < TS; s++) {
            int t = g * TS + s;
            float eg = egsh[t], bt = bsh[t];
            float vv = vsh[buf][s][col];
            const u64* kh2 = (const u64*)&ksh[buf][s][half * 32];
            const u64* qh2 = (const u64*)&qsh[buf][s][half * 32];

            u64 eg2; DUP2(eg2, __float_as_uint(eg));
            u64 p0 = 0ull, p1 = 0ull, p2 = 0ull, p3 = 0ull;
#pragma unroll
            for (int j = 0; j < 16; j += 4) {
                MUL2(S2[j],     S2[j],     eg2);
                MUL2(S2[j + 1], S2[j + 1], eg2);
                MUL2(S2[j + 2], S2[j + 2], eg2);
                MUL2(S2[j + 3], S2[j + 3], eg2);
                FMA2(p0, kh2[j],     S2[j]);
                FMA2(p1, kh2[j + 1], S2[j + 1]);
                FMA2(p2, kh2[j + 2], S2[j + 2]);
                FMA2(p3, kh2[j + 3], S2[j + 3]);
            }
            u32 a0, a1, a2, a3, a4, a5, a6, a7;
            UNPK2(a0, a1, p0); UNPK2(a2, a3, p1);
            UNPK2(a4, a5, p2); UNPK2(a6, a7, p3);
            float pred = ((__uint_as_float(a0) + __uint_as_float(a1)) +
                          (__uint_as_float(a2) + __uint_as_float(a3))) +
                         ((__uint_as_float(a4) + __uint_as_float(a5)) +
                          (__uint_as_float(a6) + __uint_as_float(a7)));
            pred += __shfl_xor_sync(0xffffffffu, pred, 1);
            float delta = bt * (vv - pred);

            u64 d2; DUP2(d2, __float_as_uint(delta));
            u64 o0 = 0ull, o1 = 0ull, o2 = 0ull, o3 = 0ull;
#pragma unroll
            for (int j = 0; j < 16; j += 4) {
                FMA2(S2[j],     kh2[j],     d2);
                FMA2(S2[j + 1], kh2[j + 1], d2);
                FMA2(S2[j + 2], kh2[j + 2], d2);
                FMA2(S2[j + 3], kh2[j + 3], d2);
                FMA2(o0, qh2[j],     S2[j]);
                FMA2(o1, qh2[j + 1], S2[j + 1]);
                FMA2(o2, qh2[j + 2], S2[j + 2]);
                FMA2(o3, qh2[j + 3], S2[j + 3]);
            }
            UNPK2(a0, a1, o0); UNPK2(a2, a3, o1);
            UNPK2(a4, a5, o2); UNPK2(a6, a7, o3);
            float out = ((__uint_as_float(a0) + __uint_as_float(a1)) +
                         (__uint_as_float(a2) + __uint_as_float(a3))) +
                        ((__uint_as_float(a4) + __uint_as_float(a5)) +
                         (__uint_as_float(a6) + __uint_as_float(a7)));
            out += __shfl_xor_sync(0xffffffffu, out, 1);
            if (half == 0) ob[(size_t)t * VD + col] = out;
        }
        if (more) {
#pragma unroll
            for (int i = 0; i < TS / 2; i++) {
                int s = i * 2 + ls;
                ksh[buf ^ 1][s][lc] = rk[i];
                qsh[buf ^ 1][s][lc] = rq[i];
                vsh[buf ^ 1][s][lc] = rv[i];
            }
        }
        __syncthreads();
    }
}

// ================= rmsnorm * gnorm_w * silu(g) -> hi/lo bf16 =================
__global__ void rmsgate_kernel(const float* __restrict__ o, const float* __restrict__ g,
                               const float* __restrict__ gw,
                               __nv_bfloat16* __restrict__ oh, __nv_bfloat16* __restrict__ ol) {
    int bl = blockIdx.x / NHH, h = blockIdx.x % NHH;
    size_t obase = (size_t)blockIdx.x * DVV;
    size_t gbase = (size_t)bl * NTOT + h * DVV;
    int tid = threadIdx.x;
    float val = o[obase + tid];
    float ss = val * val;
#pragma unroll
    for (int off = 16; off; off >>= 1) ss += __shfl_xor_sync(0xffffffffu, ss, off);
    __shared__ float sr[4];
    if ((tid & 31) == 0) sr[tid >> 5] = ss;
    __syncthreads();
    float tot = sr[0] + sr[1] + sr[2] + sr[3];
    float r = rsqrtf(tot / DVV + 1e-5f);
    float gv = g[gbase + tid];
    float sgt = gv / (1.f + expf(-gv));
    float res = val * r * gw[tid] * sgt;
    __nv_bfloat16 hi = __float2bfloat16(res);
    oh[obase + tid] = hi;
    ol[obase + tid] = __float2bfloat16(res - __bfloat162float(hi));
}

// ================= launch =================
extern "C" void kernel_launch(void* const* d_in, const int* in_sizes, int n_in,
                              void* d_out, int out_size) {
    const float *hs = 0, *Wq = 0, *Wk = 0, *Wv = 0, *Wg = 0, *Wgk = 0, *Wb = 0,
                *bbp = 0, *convq = 0, *convk = 0, *convv = 0, *Alog = 0,
                *dtb = 0, *gnw = 0, *Wo = 0;
    int c786 = 0, c1572 = 0, c12288 = 0, c12 = 0, c3072 = 0;
    for (int i = 0; i < n_in; i++) {
        const float* p = (const float*)d_in[i];
        switch (in_sizes[i]) {
            case 8388608: hs = p; break;
            case 786432:  if (c786++ == 0) Wq = p; else Wk = p; break;
            case 1572864: { int j = c1572++; if (j == 0) Wv = p; else if (j == 1) Wg = p; else Wo = p; } break;
            case 12288:   if (c12288++ == 0) Wgk = p; else Wb = p; break;
            case 12:      { int j = c12++; if (j == 0) bbp = p; else if (j == 1) Alog = p; else dtb = p; } break;
            case 3072:    if (c3072++ == 0) convq = p; else convk = p; break;
            case 6144:    convv = p; break;
            case 128:     gnw = p; break;
            default: break;
        }
    }

    float *qkvg, *bQc, *bKc, *bVc, *bO, *bgk, *bbe;
    __nv_bfloat16 *hsh, *hsl, *wth, *wtl, *woth, *wotl, *oh, *ol;
    cudaGetSymbolAddress((void**)&qkvg, g_qkvg);
    cudaGetSymbolAddress((void**)&hsh,  g_hsh);
    cudaGetSymbolAddress((void**)&hsl,  g_hsl);
    cudaGetSymbolAddress((void**)&wth,  g_wth);
    cudaGetSymbolAddress((void**)&wtl,  g_wtl);
    cudaGetSymbolAddress((void**)&woth, g_woth);
    cudaGetSymbolAddress((void**)&wotl, g_wotl);
    cudaGetSymbolAddress((void**)&oh,   g_oh);
    cudaGetSymbolAddress((void**)&ol,   g_ol);
    cudaGetSymbolAddress((void**)&bQc,  g_bufQc);
    cudaGetSymbolAddress((void**)&bKc,  g_bufKc);
    cudaGetSymbolAddress((void**)&bVc,  g_bufVc);
    cudaGetSymbolAddress((void**)&bO,   g_bufO);
    cudaGetSymbolAddress((void**)&bgk,  g_gk);
    cudaGetSymbolAddress((void**)&bbe,  g_beta);

    cudaFuncSetAttribute(gemm_mma, cudaFuncAttributeMaxDynamicSharedMemorySize, SMEM_GEMM);

    // 1: split, 2: transposes, 3: QKVG projection
    split_kernel<<<(BL * HH + 255) / 256, 256>>>(hs, hsh, hsl, BL * HH);
    transp_all<<<6144, dim3(32, 8)>>>(Wq, Wk, Wv, Wg, Wo, wth, wtl, woth, wotl);
    gemm_mma<<<dim3(NTOT / 128, BL / 128), 256, SMEM_GEMM>>>(hsh, hsl, wth, wtl, qkvg, HH, NTOT);

    // 4: convqk (capture slot), 5: convv, 6: gkbeta
    conv_silu_l2qk<<<BL * NHH * 2 / 4, 256>>>(qkvg, convq, convk, bQc, bKc);
    int totv = BL * VD;
    conv_silu_v<<<(totv + 255) / 256, 256>>>(qkvg + 1536, NTOT, convv, bVc, totv);
    gkbeta2<<<BL / 8, 256>>>(hs, Wgk, Wb, bbp, Alog, dtb, bgk, bbe);

    // 7: recurrence
    recur5<<<BB * NHH * 2, 128>>>(bQc, bKc, bVc, bgk, bbe, bO);

    // 8: rmsnorm + swish gate
    rmsgate_kernel<<<BL * NHH, 128>>>(bO, qkvg + 3072, gnw, oh, ol);

    // 9: output projection
    gemm_mma<<<dim3(HH / 128, BL / 128), 256, SMEM_GEMM>>>(oh, ol, woth, wotl, (float*)d_out, VD, HH);
}

// round 15
// speedup vs baseline: 1.5299x; 1.5299x over previous
#include <cuda_runtime.h>
#include <cuda_bf16.h>
#include <math.h>
#include <cstdint>

#define NHH 12
#define DKK 64
#define DVV 128
#define BB  4
#define LL  2048
#define HH  1024
#define KD  768
#define VD  1536
#define BL  (BB*LL)
#define NTOT 4608

typedef unsigned long long u64;
typedef unsigned int u32;

#define FMA2(c, a, b) asm("fma.rn.f32x2 %0, %1, %2, %0;" : "+l"(c) : "l"(a), "l"(b))
#define MUL2(d, a, b) asm("mul.rn.f32x2 %0, %1, %2;" : "=l"(d) : "l"(a), "l"(b))
#define DUP2(d, s)    asm("mov.b64 %0, {%1, %1};" : "=l"(d) : "r"(s))
#define UNPK2(lo, hi, v) asm("mov.b64 {%0, %1}, %2;" : "=r"(lo), "=r"(hi) : "l"(v))

__device__ __forceinline__ uint32_t smem_to_u32(const void* p) {
    uint32_t a;
    asm("{ .reg .u64 t; cvta.to.shared.u64 t, %1; cvt.u32.u64 %0, t; }" : "=r"(a) : "l"(p));
    return a;
}

#define LDSM4(r0, r1, r2, r3, addr) \
    asm volatile("ldmatrix.sync.aligned.m8n8.x4.shared.b16 {%0,%1,%2,%3}, [%4];" \
        : "=r"(r0), "=r"(r1), "=r"(r2), "=r"(r3) : "r"(addr))

#define MMA16816(c, a, b0, b1) \
    asm volatile("mma.sync.aligned.m16n8k16.row.col.f32.bf16.bf16.f32 " \
        "{%0,%1,%2,%3},{%4,%5,%6,%7},{%8,%9},{%0,%1,%2,%3};" \
        : "+f"((c)[0]), "+f"((c)[1]), "+f"((c)[2]), "+f"((c)[3]) \
        : "r"((a)[0]), "r"((a)[1]), "r"((a)[2]), "r"((a)[3]), "r"(b0), "r"(b1))

__device__ __forceinline__ void cpa16(uint32_t saddr, const void* g) {
    asm volatile("cp.async.cg.shared.global [%0], [%1], 16;" :: "r"(saddr), "l"(g));
}
#define CP_COMMIT() asm volatile("cp.async.commit_group;" ::: "memory")
#define CP_WAIT0()  asm volatile("cp.async.wait_group 0;" ::: "memory")

// ================= scratch =================
__device__ float g_qkvg[(size_t)BL * NTOT];
__device__ __nv_bfloat16 g_hsh[(size_t)BL * HH], g_hsl[(size_t)BL * HH];
__device__ __nv_bfloat16 g_wth[(size_t)NTOT * HH], g_wtl[(size_t)NTOT * HH];
__device__ __nv_bfloat16 g_woth[(size_t)HH * VD], g_wotl[(size_t)HH * VD];
__device__ __nv_bfloat16 g_oh[(size_t)BL * VD], g_ol[(size_t)BL * VD];
__device__ float g_bufQc[BL*KD], g_bufKc[BL*KD], g_bufVc[BL*VD], g_bufO[BL*VD];
__device__ float g_gk[BL*NHH], g_beta[BL*NHH];

// ================= hi/lo split =================
__global__ void split_kernel(const float* __restrict__ in,
                             __nv_bfloat16* __restrict__ oh, __nv_bfloat16* __restrict__ ol, int n) {
    int i = blockIdx.x * 256 + threadIdx.x;
    if (i >= n) return;
    float x = in[i];
    __nv_bfloat16 h = __float2bfloat16(x);
    oh[i] = h;
    ol[i] = __float2bfloat16(x - __bfloat162float(h));
}

// ================= fused transpose+split of all 5 weight matrices =================
__device__ __forceinline__ void transp_tile(const float* __restrict__ W, int K, int N,
                                            __nv_bfloat16* __restrict__ Th,
                                            __nv_bfloat16* __restrict__ Tl,
                                            int n0, int k0, float* tile) {
    int tx = threadIdx.x, ty = threadIdx.y;
    for (int i = ty; i < 32; i += 8)
        tile[i * 33 + tx] = W[(size_t)(k0 + i) * N + n0 + tx];
    __syncthreads();
    for (int i = ty; i < 32; i += 8) {
        float x = tile[tx * 33 + i];
        __nv_bfloat16 h = __float2bfloat16(x);
        size_t o = (size_t)(n0 + i) * K + k0 + tx;
        Th[o] = h;
        Tl[o] = __float2bfloat16(x - __bfloat162float(h));
    }
}

__global__ void transp_all(const float* __restrict__ Wq, const float* __restrict__ Wk,
                           const float* __restrict__ Wv, const float* __restrict__ Wg,
                           const float* __restrict__ Wo,
                           __nv_bfloat16* __restrict__ wth, __nv_bfloat16* __restrict__ wtl,
                           __nv_bfloat16* __restrict__ woth, __nv_bfloat16* __restrict__ wotl) {
    __shared__ float tile[32 * 33];
    int idx = blockIdx.x;
    if (idx < 768) {
        transp_tile(Wq, HH, KD, wth, wtl, (idx % 24) * 32, (idx / 24) * 32, tile);
    } else if (idx < 1536) {
        idx -= 768;
        transp_tile(Wk, HH, KD, wth + (size_t)768 * HH, wtl + (size_t)768 * HH,
                    (idx % 24) * 32, (idx / 24) * 32, tile);
    } else if (idx < 3072) {
        idx -= 1536;
        transp_tile(Wv, HH, VD, wth + (size_t)1536 * HH, wtl + (size_t)1536 * HH,
                    (idx % 48) * 32, (idx / 48) * 32, tile);
    } else if (idx < 4608) {
        idx -= 3072;
        transp_tile(Wg, HH, VD, wth + (size_t)3072 * HH, wtl + (size_t)3072 * HH,
                    (idx % 48) * 32, (idx / 48) * 32, tile);
    } else {
        idx -= 4608;
        transp_tile(Wo, VD, HH, woth, wotl, (idx % 32) * 32, (idx / 32) * 32, tile);
    }
}

// ================= mma.sync split-bf16 GEMM (128x128, 2 CTA/SM) =================
#define TILE_B 10240
#define SMEM_GEMM (8 * TILE_B)

__global__ void __launch_bounds__(256, 2)
gemm_mma(const __nv_bfloat16* __restrict__ Ahi, const __nv_bfloat16* __restrict__ Alo,
         const __nv_bfloat16* __restrict__ Bhi, const __nv_bfloat16* __restrict__ Blo,
         float* __restrict__ C, int Kdim, int ldc) {
    extern __shared__ char smem[];
    const uint32_t smb = smem_to_u32(smem);
    const int tid = threadIdx.x;
    const int lane = tid & 31, w = tid >> 5;
    const int wm = (w & 1) * 64, wn = (w >> 1) * 32;
    const int m0 = blockIdx.y * 128, n0 = blockIdx.x * 128;

    const int rL = tid >> 1;
    const int qL = (tid & 1) * 2;

    float c[4][4][4];
#pragma unroll
    for (int i = 0; i < 4; i++)
#pragma unroll
        for (int j = 0; j < 4; j++)
#pragma unroll
            for (int e = 0; e < 4; e++) c[i][j][e] = 0.f;

    const int nCh = Kdim >> 5;

    auto load_stage = [&](int kc, int st) {
        const __nv_bfloat16* a0 = Ahi + (size_t)(m0 + rL) * Kdim + kc * 32 + qL * 8;
        const __nv_bfloat16* a1 = Alo + (size_t)(m0 + rL) * Kdim + kc * 32 + qL * 8;
        const __nv_bfloat16* b0 = Bhi + (size_t)(n0 + rL) * Kdim + kc * 32 + qL * 8;
        const __nv_bfloat16* b1 = Blo + (size_t)(n0 + rL) * Kdim + kc * 32 + qL * 8;
        uint32_t sa0 = smb + (st * 2 + 0) * TILE_B + rL * 80 + qL * 16;
        uint32_t sa1 = smb + (st * 2 + 1) * TILE_B + rL * 80 + qL * 16;
        uint32_t sb0 = smb + 4 * TILE_B + (st * 2 + 0) * TILE_B + rL * 80 + qL * 16;
        uint32_t sb1 = smb + 4 * TILE_B + (st * 2 + 1) * TILE_B + rL * 80 + qL * 16;
        cpa16(sa0, a0); cpa16(sa0 + 16, a0 + 8);
        cpa16(sa1, a1); cpa16(sa1 + 16, a1 + 8);
        cpa16(sb0, b0); cpa16(sb0 + 16, b0 + 8);
        cpa16(sb1, b1); cpa16(sb1 + 16, b1 + 8);
        CP_COMMIT();
    };

    load_stage(0, 0);

    for (int kc = 0; kc < nCh; kc++) {
        const int st = kc & 1;
        CP_WAIT0();
        __syncthreads();
        if (kc + 1 < nCh) load_stage(kc + 1, st ^ 1);

        const int lrow = lane & 15;
        const int lcolB = ((lane >> 4) << 3) * 2;
#pragma unroll
        for (int ks = 0; ks < 2; ks++) {
            const int kbB = ks * 32 + lcolB;
            uint32_t bh[2][4], bl[2][4];
#pragma unroll
            for (int np = 0; np < 2; np++) {
                int row = wn + np * 16 + lrow;
                uint32_t bd = smb + 4 * TILE_B + st * 2 * TILE_B + row * 80 + kbB;
                LDSM4(bh[np][0], bh[np][1], bh[np][2], bh[np][3], bd);
                LDSM4(bl[np][0], bl[np][1], bl[np][2], bl[np][3], bd + TILE_B);
            }
#pragma unroll
            for (int mt = 0; mt < 4; mt++) {
                uint32_t ah[4], al[4];
                int row = wm + mt * 16 + lrow;
                uint32_t ad = smb + st * 2 * TILE_B + row * 80 + kbB;
                LDSM4(ah[0], ah[1], ah[2], ah[3], ad);
                LDSM4(al[0], al[1], al[2], al[3], ad + TILE_B);
#pragma unroll
                for (int nt = 0; nt < 4; nt++) {
                    int np = nt >> 1, s = nt & 1;
                    MMA16816(c[mt][nt], ah, bh[np][s], bh[np][s + 2]);
                    MMA16816(c[mt][nt], ah, bl[np][s], bl[np][s + 2]);
                    MMA16816(c[mt][nt], al, bh[np][s], bh[np][s + 2]);
                }
            }
        }
    }
    CP_WAIT0();

#pragma unroll
    for (int mt = 0; mt < 4; mt++) {
        int row = m0 + wm + mt * 16 + (lane >> 2);
#pragma unroll
        for (int nt = 0; nt < 4; nt++) {
            int col = n0 + wn + nt * 8 + (lane & 3) * 2;
            *(float2*)(C + (size_t)row * ldc + col)       = make_float2(c[mt][nt][0], c[mt][nt][1]);
            *(float2*)(C + (size_t)(row + 8) * ldc + col) = make_float2(c[mt][nt][2], c[mt][nt][3]);
        }
    }
}

// ================= gk / beta projection =================
__global__ void gkbeta2(const float* __restrict__ hs,
                        const float* __restrict__ Wgk, const float* __restrict__ Wb,
                        const float* __restrict__ bb,  const float* __restrict__ A_log,
                        const float* __restrict__ dt_bias,
                        float* __restrict__ gk, float* __restrict__ beta) {
    __shared__ float sh[8][HH];
    int w = threadIdx.x >> 5, lane = threadIdx.x & 31;
    int row = blockIdx.x * 8 + w;
    const float* hr = hs + (size_t)row * HH;
    for (int i = lane; i < HH; i += 32) sh[w][i] = hr[i];
    __syncwarp();
    if (lane < 24) {
        const float* W = (lane < 12) ? Wgk : Wb;
        int j = (lane < 12) ? lane : lane - 12;
        float acc = 0.f;
#pragma unroll 4
        for (int k = 0; k < HH; k++) acc += sh[w][k] * W[k * NHH + j];
        if (lane < 12) {
            acc += dt_bias[j];
            float sp = (acc > 20.f) ? acc : log1pf(expf(acc));
            gk[row * NHH + j] = -expf(A_log[j]) * sp;
        } else {
            acc += bb[j];
            beta[row * NHH + j] = 1.f / (1.f + expf(-acc));
        }
    }
}

// ================= conv + silu + l2norm (q & k, 4 units per 256-thr CTA) =================
__global__ void __launch_bounds__(256)
conv_silu_l2qk(const float* __restrict__ qkvg,
               const float* __restrict__ wq, const float* __restrict__ wk,
               float* __restrict__ outq, float* __restrict__ outk) {
    __shared__ float sred[8];
    int tid  = threadIdx.x;
    int unit = tid >> 6;
    int ch   = tid & 63;
    int idx  = blockIdx.x * 4 + unit;
    int which = idx & 1;
    idx >>= 1;
    int h  = idx % NHH;
    int bl = idx / NHH;
    int l  = bl % LL;
    int c  = h * DKK + ch;
    const float* in = qkvg + (which ? 768 : 0);
    const float* wr = (which ? wk : wq) + c * 4;
    float* out = which ? outk : outq;
    float acc = 0.f;
#pragma unroll
    for (int j = 0; j < 4; j++) {
        int tt = l - 3 + j;
        if (tt >= 0) acc += in[(size_t)(bl - l + tt) * NTOT + c] * wr[j];
    }
    float sv = acc / (1.f + expf(-acc));
    float ss = sv * sv;
#pragma unroll
    for (int off = 16; off; off >>= 1) ss += __shfl_xor_sync(0xffffffffu, ss, off);
    if ((tid & 31) == 0) sred[tid >> 5] = ss;
    __syncthreads();
    float n = sqrtf(sred[unit * 2] + sred[unit * 2 + 1]);
    out[(size_t)bl * KD + c] = sv / fmaxf(n, 1e-12f);
}

__global__ void conv_silu_v(const float* __restrict__ in, int istride,
                            const float* __restrict__ w, float* __restrict__ out, int total) {
    int gid = blockIdx.x * blockDim.x + threadIdx.x;
    if (gid >= total) return;
    int c  = gid % VD;
    int bl = gid / VD;
    int l  = bl % LL;
    const float* wr = w + c * 4;
    float acc = 0.f;
#pragma unroll
    for (int j = 0; j < 4; j++) {
        int tt = l - 3 + j;
        if (tt >= 0) acc += in[(size_t)(bl - l + tt) * istride + c] * wr[j];
    }
    out[gid] = acc / (1.f + expf(-acc));
}

// ================= recurrence v5: 128 thr, 16-step groups (best known) =================
#define TS 16
__global__ void __launch_bounds__(128)
recur5(const float* __restrict__ q, const float* __restrict__ k,
       const float* __restrict__ v, const float* __restrict__ gk,
       const float* __restrict__ beta, float* __restrict__ o) {
    int blk = blockIdx.x;
    int b  = blk / (NHH * 2);
    int h  = (blk >> 1) % NHH;
    int vh = blk & 1;
    int tid = threadIdx.x;
    int col  = tid >> 1;
    int half = tid & 1;

    __shared__ float ksh[2][TS][64];
    __shared__ float qsh[2][TS][64];
    __shared__ float vsh[2][TS][64];
    __shared__ float egsh[LL];
    __shared__ float bsh[LL];

    const float* qb = q + (size_t)b * LL * KD + h * DKK;
    const float* kb = k + (size_t)b * LL * KD + h * DKK;
    const float* vb = v + (size_t)b * LL * VD + h * DVV + vh * 64;
    const float* gb = gk + (size_t)b * LL * NHH + h;
    const float* be = beta + (size_t)b * LL * NHH + h;
    float* ob = o + (size_t)b * LL * VD + h * DVV + vh * 64;

    for (int i = tid; i < LL; i += 128) {
        egsh[i] = expf(gb[(size_t)i * NHH]);
        bsh[i]  = be[(size_t)i * NHH];
    }

    u64 S2[16];
#pragma unroll
    for (int i = 0; i < 16; i++) S2[i] = 0ull;

    const int ls = tid >> 6;
    const int lc = tid & 63;
#pragma unroll
    for (int i = 0; i < TS / 2; i++) {
        int s = i * 2 + ls;
        ksh[0][s][lc] = kb[(size_t)s * KD + lc];
        qsh[0][s][lc] = qb[(size_t)s * KD + lc];
        vsh[0][s][lc] = vb[(size_t)s * VD + lc];
    }
    __syncthreads();

    const int NG = LL / TS;
    for (int g = 0; g < NG; g++) {
        const int buf = g & 1;
        float rk[TS / 2], rq[TS / 2], rv[TS / 2];
        const bool more = (g + 1) < NG;
        if (more) {
            int t0 = (g + 1) * TS;
#pragma unroll
            for (int i = 0; i < TS / 2; i++) {
                int s = i * 2 + ls;
                rk[i] = kb[(size_t)(t0 + s) * KD + lc];
                rq[i] = qb[(size_t)(t0 + s) * KD + lc];
                rv[i] = vb[(size_t)(t0 + s) * VD + lc];
            }
        }
#pragma unroll
        for (int s = 0; s < TS; s++) {
            int t = g * TS + s;
            float eg = egsh[t], bt = bsh[t];
            float vv = vsh[buf][s][col];
            const u64* kh2 = (const u64*)&ksh[buf][s][half * 32];
            const u64* qh2 = (const u64*)&qsh[buf][s][half * 32];

            u64 eg2; DUP2(eg2, __float_as_uint(eg));
            u64 p0 = 0ull, p1 = 0ull, p2 = 0ull, p3 = 0ull;
#pragma unroll
            for (int j = 0; j < 16; j += 4) {
                MUL2(S2[j],     S2[j],     eg2);
                MUL2(S2[j + 1], S2[j + 1], eg2);
                MUL2(S2[j + 2], S2[j + 2], eg2);
                MUL2(S2[j + 3], S2[j + 3], eg2);
                FMA2(p0, kh2[j],     S2[j]);
                FMA2(p1, kh2[j + 1], S2[j + 1]);
                FMA2(p2, kh2[j + 2], S2[j + 2]);
                FMA2(p3, kh2[j + 3], S2[j + 3]);
            }
            u32 a0, a1, a2, a3, a4, a5, a6, a7;
            UNPK2(a0, a1, p0); UNPK2(a2, a3, p1);
            UNPK2(a4, a5, p2); UNPK2(a6, a7, p3);
            float pred = ((__uint_as_float(a0) + __uint_as_float(a1)) +
                          (__uint_as_float(a2) + __uint_as_float(a3))) +
                         ((__uint_as_float(a4) + __uint_as_float(a5)) +
                          (__uint_as_float(a6) + __uint_as_float(a7)));
            pred += __shfl_xor_sync(0xffffffffu, pred, 1);
            float delta = bt * (vv - pred);

            u64 d2; DUP2(d2, __float_as_uint(delta));
            u64 o0 = 0ull, o1 = 0ull, o2 = 0ull, o3 = 0ull;
#pragma unroll
            for (int j = 0; j < 16; j += 4) {
                FMA2(S2[j],     kh2[j],     d2);
                FMA2(S2[j + 1], kh2[j + 1], d2);
                FMA2(S2[j + 2], kh2[j + 2], d2);
                FMA2(S2[j + 3], kh2[j + 3], d2);
                FMA2(o0, qh2[j],     S2[j]);
                FMA2(o1, qh2[j + 1], S2[j + 1]);
                FMA2(o2, qh2[j + 2], S2[j + 2]);
                FMA2(o3, qh2[j + 3], S2[j + 3]);
            }
            UNPK2(a0, a1, o0); UNPK2(a2, a3, o1);
            UNPK2(a4, a5, o2); UNPK2(a6, a7, o3);
            float out = ((__uint_as_float(a0) + __uint_as_float(a1)) +
                         (__uint_as_float(a2) + __uint_as_float(a3))) +
                        ((__uint_as_float(a4) + __uint_as_float(a5)) +
                         (__uint_as_float(a6) + __uint_as_float(a7)));
            out += __shfl_xor_sync(0xffffffffu, out, 1);
            if (half == 0) ob[(size_t)t * VD + col] = out;
        }
        if (more) {
#pragma unroll
            for (int i = 0; i < TS / 2; i++) {
                int s = i * 2 + ls;
                ksh[buf ^ 1][s][lc] = rk[i];
                qsh[buf ^ 1][s][lc] = rq[i];
                vsh[buf ^ 1][s][lc] = rv[i];
            }
        }
        __syncthreads();
    }
}

// ================= rmsnorm * gnorm_w * silu(g) -> hi/lo bf16 =================
__global__ void rmsgate_kernel(const float* __restrict__ o, const float* __restrict__ g,
                               const float* __restrict__ gw,
                               __nv_bfloat16* __restrict__ oh, __nv_bfloat16* __restrict__ ol) {
    int bl = blockIdx.x / NHH, h = blockIdx.x % NHH;
    size_t obase = (size_t)blockIdx.x * DVV;
    size_t gbase = (size_t)bl * NTOT + h * DVV;
    int tid = threadIdx.x;
    float val = o[obase + tid];
    float ss = val * val;
#pragma unroll
    for (int off = 16; off; off >>= 1) ss += __shfl_xor_sync(0xffffffffu, ss, off);
    __shared__ float sr[4];
    if ((tid & 31) == 0) sr[tid >> 5] = ss;
    __syncthreads();
    float tot = sr[0] + sr[1] + sr[2] + sr[3];
    float r = rsqrtf(tot / DVV + 1e-5f);
    float gv = g[gbase + tid];
    float sgt = gv / (1.f + expf(-gv));
    float res = val * r * gw[tid] * sgt;
    __nv_bfloat16 hi = __float2bfloat16(res);
    oh[obase + tid] = hi;
    ol[obase + tid] = __float2bfloat16(res - __bfloat162float(hi));
}

// ================= launch =================
extern "C" void kernel_launch(void* const* d_in, const int* in_sizes, int n_in,
                              void* d_out, int out_size) {
    const float *hs = 0, *Wq = 0, *Wk = 0, *Wv = 0, *Wg = 0, *Wgk = 0, *Wb = 0,
                *bbp = 0, *convq = 0, *convk = 0, *convv = 0, *Alog = 0,
                *dtb = 0, *gnw = 0, *Wo = 0;
    int c786 = 0, c1572 = 0, c12288 = 0, c12 = 0, c3072 = 0;
    for (int i = 0; i < n_in; i++) {
        const float* p = (const float*)d_in[i];
        switch (in_sizes[i]) {
            case 8388608: hs = p; break;
            case 786432:  if (c786++ == 0) Wq = p; else Wk = p; break;
            case 1572864: { int j = c1572++; if (j == 0) Wv = p; else if (j == 1) Wg = p; else Wo = p; } break;
            case 12288:   if (c12288++ == 0) Wgk = p; else Wb = p; break;
            case 12:      { int j = c12++; if (j == 0) bbp = p; else if (j == 1) Alog = p; else dtb = p; } break;
            case 3072:    if (c3072++ == 0) convq = p; else convk = p; break;
            case 6144:    convv = p; break;
            case 128:     gnw = p; break;
            default: break;
        }
    }

    float *qkvg, *bQc, *bKc, *bVc, *bO, *bgk, *bbe;
    __nv_bfloat16 *hsh, *hsl, *wth, *wtl, *woth, *wotl, *oh, *ol;
    cudaGetSymbolAddress((void**)&qkvg, g_qkvg);
    cudaGetSymbolAddress((void**)&hsh,  g_hsh);
    cudaGetSymbolAddress((void**)&hsl,  g_hsl);
    cudaGetSymbolAddress((void**)&wth,  g_wth);
    cudaGetSymbolAddress((void**)&wtl,  g_wtl);
    cudaGetSymbolAddress((void**)&woth, g_woth);
    cudaGetSymbolAddress((void**)&wotl, g_wotl);
    cudaGetSymbolAddress((void**)&oh,   g_oh);
    cudaGetSymbolAddress((void**)&ol,   g_ol);
    cudaGetSymbolAddress((void**)&bQc,  g_bufQc);
    cudaGetSymbolAddress((void**)&bKc,  g_bufKc);
    cudaGetSymbolAddress((void**)&bVc,  g_bufVc);
    cudaGetSymbolAddress((void**)&bO,   g_bufO);
    cudaGetSymbolAddress((void**)&bgk,  g_gk);
    cudaGetSymbolAddress((void**)&bbe,  g_beta);

    cudaFuncSetAttribute(gemm_mma, cudaFuncAttributeMaxDynamicSharedMemorySize, SMEM_GEMM);

    // round-10 launch order: split, transposes, gkbeta, QKVG gemm, convs, recur, rmsgate, out gemm
    split_kernel<<<(BL * HH + 255) / 256, 256>>>(hs, hsh, hsl, BL * HH);
    transp_all<<<6144, dim3(32, 8)>>>(Wq, Wk, Wv, Wg, Wo, wth, wtl, woth, wotl);
    gkbeta2<<<BL / 8, 256>>>(hs, Wgk, Wb, bbp, Alog, dtb, bgk, bbe);

    gemm_mma<<<dim3(NTOT / 128, BL / 128), 256, SMEM_GEMM>>>(hsh, hsl, wth, wtl, qkvg, HH, NTOT);

    conv_silu_l2qk<<<BL * NHH * 2 / 4, 256>>>(qkvg, convq, convk, bQc, bKc);
    int totv = BL * VD;
    conv_silu_v<<<(totv + 255) / 256, 256>>>(qkvg + 1536, NTOT, convv, bVc, totv);

    recur5<<<BB * NHH * 2, 128>>>(bQc, bKc, bVc, bgk, bbe, bO);

    rmsgate_kernel<<<BL * NHH, 128>>>(bO, qkvg + 3072, gnw, oh, ol);

    gemm_mma<<<dim3(HH / 128, BL / 128), 256, SMEM_GEMM>>>(oh, ol, woth, wotl, (float*)d_out, VD, HH);
}

// round 16
// speedup vs baseline: 1.8317x; 1.1973x over previous
#include <cuda_runtime.h>
#include <cuda_fp16.h>
#include <math.h>
#include <cstdint>

#define NHH 12
#define DKK 64
#define DVV 128
#define BB  4
#define LL  2048
#define HH  1024
#define KD  768
#define VD  1536
#define BL  (BB*LL)
#define NTOT 4608

typedef unsigned long long u64;
typedef unsigned int u32;

#define FMA2(c, a, b) asm("fma.rn.f32x2 %0, %1, %2, %0;" : "+l"(c) : "l"(a), "l"(b))
#define MUL2(d, a, b) asm("mul.rn.f32x2 %0, %1, %2;" : "=l"(d) : "l"(a), "l"(b))
#define DUP2(d, s)    asm("mov.b64 %0, {%1, %1};" : "=l"(d) : "r"(s))
#define UNPK2(lo, hi, v) asm("mov.b64 {%0, %1}, %2;" : "=r"(lo), "=r"(hi) : "l"(v))

__device__ __forceinline__ uint32_t smem_to_u32(const void* p) {
    uint32_t a;
    asm("{ .reg .u64 t; cvta.to.shared.u64 t, %1; cvt.u32.u64 %0, t; }" : "=r"(a) : "l"(p));
    return a;
}

#define LDSM4(r0, r1, r2, r3, addr) \
    asm volatile("ldmatrix.sync.aligned.m8n8.x4.shared.b16 {%0,%1,%2,%3}, [%4];" \
        : "=r"(r0), "=r"(r1), "=r"(r2), "=r"(r3) : "r"(addr))

#define MMAH16816(c, a, b0, b1) \
    asm volatile("mma.sync.aligned.m16n8k16.row.col.f32.f16.f16.f32 " \
        "{%0,%1,%2,%3},{%4,%5,%6,%7},{%8,%9},{%0,%1,%2,%3};" \
        : "+f"((c)[0]), "+f"((c)[1]), "+f"((c)[2]), "+f"((c)[3]) \
        : "r"((a)[0]), "r"((a)[1]), "r"((a)[2]), "r"((a)[3]), "r"(b0), "r"(b1))

__device__ __forceinline__ void cpa16(uint32_t saddr, const void* g) {
    asm volatile("cp.async.cg.shared.global [%0], [%1], 16;" :: "r"(saddr), "l"(g));
}
#define CP_COMMIT() asm volatile("cp.async.commit_group;" ::: "memory")
#define CP_WAIT1()  asm volatile("cp.async.wait_group 1;" ::: "memory")
#define CP_WAIT0()  asm volatile("cp.async.wait_group 0;" ::: "memory")

// ================= scratch =================
__device__ float g_qkvg[(size_t)BL * NTOT];
__device__ __half g_hsh[(size_t)BL * HH], g_hsl[(size_t)BL * HH];
__device__ __half g_wth[(size_t)NTOT * HH];
__device__ __half g_woth[(size_t)HH * VD];
__device__ __half g_oh[(size_t)BL * VD], g_ol[(size_t)BL * VD];
__device__ float g_bufQc[BL*KD], g_bufKc[BL*KD], g_bufVc[BL*VD], g_bufO[BL*VD];
__device__ float g_gk[BL*NHH], g_beta[BL*NHH];

// ================= fp16 hi/lo split of activations =================
__global__ void split_kernel(const float* __restrict__ in,
                             __half* __restrict__ oh, __half* __restrict__ ol, int n) {
    int i = blockIdx.x * 256 + threadIdx.x;
    if (i >= n) return;
    float x = in[i];
    __half h = __float2half_rn(x);
    oh[i] = h;
    ol[i] = __float2half_rn(x - __half2float(h));
}

// ================= fused transpose (fp16, hi only) of all 5 weight matrices =================
__device__ __forceinline__ void transp_tile(const float* __restrict__ W, int K, int N,
                                            __half* __restrict__ Th,
                                            int n0, int k0, float* tile) {
    int tx = threadIdx.x, ty = threadIdx.y;
    for (int i = ty; i < 32; i += 8)
        tile[i * 33 + tx] = W[(size_t)(k0 + i) * N + n0 + tx];
    __syncthreads();
    for (int i = ty; i < 32; i += 8) {
        float x = tile[tx * 33 + i];
        Th[(size_t)(n0 + i) * K + k0 + tx] = __float2half_rn(x);
    }
}

__global__ void transp_all(const float* __restrict__ Wq, const float* __restrict__ Wk,
                           const float* __restrict__ Wv, const float* __restrict__ Wg,
                           const float* __restrict__ Wo,
                           __half* __restrict__ wth, __half* __restrict__ woth) {
    __shared__ float tile[32 * 33];
    int idx = blockIdx.x;
    if (idx < 768) {
        transp_tile(Wq, HH, KD, wth, (idx % 24) * 32, (idx / 24) * 32, tile);
    } else if (idx < 1536) {
        idx -= 768;
        transp_tile(Wk, HH, KD, wth + (size_t)768 * HH,
                    (idx % 24) * 32, (idx / 24) * 32, tile);
    } else if (idx < 3072) {
        idx -= 1536;
        transp_tile(Wv, HH, VD, wth + (size_t)1536 * HH,
                    (idx % 48) * 32, (idx / 48) * 32, tile);
    } else if (idx < 4608) {
        idx -= 3072;
        transp_tile(Wg, HH, VD, wth + (size_t)3072 * HH,
                    (idx % 48) * 32, (idx / 48) * 32, tile);
    } else {
        idx -= 4608;
        transp_tile(Wo, VD, HH, woth, (idx % 32) * 32, (idx / 32) * 32, tile);
    }
}

// ================= fp16 split GEMM: C = (Ahi+Alo) x Bhi, 2 passes, 3-stage pipeline =================
// 128x128 tile, BK=32, 256 thr (8 warps 2x4, warp tile 64x32).
// stage = Ahi(10240)+Alo(10240)+Bhi(10240) = 30720 B; 3 stages = 92160 B; 2 CTA/SM.
#define TILE_B 10240
#define STAGE3 30720
#define SMEM_GEMM (3 * STAGE3)

__global__ void __launch_bounds__(256, 2)
gemm_mma(const __half* __restrict__ Ahi, const __half* __restrict__ Alo,
         const __half* __restrict__ Bhi,
         float* __restrict__ C, int Kdim, int ldc) {
    extern __shared__ char smem[];
    const uint32_t smb = smem_to_u32(smem);
    const int tid = threadIdx.x;
    const int lane = tid & 31, w = tid >> 5;
    const int wm = (w & 1) * 64, wn = (w >> 1) * 32;
    const int m0 = blockIdx.y * 128, n0 = blockIdx.x * 128;

    const int rL = tid >> 1;
    const int qL = (tid & 1) * 2;

    float c[4][4][4];
#pragma unroll
    for (int i = 0; i < 4; i++)
#pragma unroll
        for (int j = 0; j < 4; j++)
#pragma unroll
            for (int e = 0; e < 4; e++) c[i][j][e] = 0.f;

    const int nCh = Kdim >> 5;

    auto load_stage = [&](int kc, int st) {
        const __half* a0 = Ahi + (size_t)(m0 + rL) * Kdim + kc * 32 + qL * 8;
        const __half* a1 = Alo + (size_t)(m0 + rL) * Kdim + kc * 32 + qL * 8;
        const __half* b0 = Bhi + (size_t)(n0 + rL) * Kdim + kc * 32 + qL * 8;
        uint32_t base = smb + st * STAGE3 + rL * 80 + qL * 16;
        cpa16(base, a0);                cpa16(base + 16, a0 + 8);
        cpa16(base + TILE_B, a1);       cpa16(base + TILE_B + 16, a1 + 8);
        cpa16(base + 2 * TILE_B, b0);   cpa16(base + 2 * TILE_B + 16, b0 + 8);
        CP_COMMIT();
    };

    load_stage(0, 0);
    load_stage(1, 1);

    for (int kc = 0; kc < nCh; kc++) {
        const int st = kc % 3;
        CP_WAIT1();
        __syncthreads();
        if (kc + 2 < nCh) load_stage(kc + 2, (kc + 2) % 3);

        const int lrow = lane & 15;
        const int lcolB = ((lane >> 4) << 3) * 2;
        const uint32_t base = smb + st * STAGE3;
#pragma unroll
        for (int ks = 0; ks < 2; ks++) {
            const int kbB = ks * 32 + lcolB;
            uint32_t bh[2][4];
#pragma unroll
            for (int np = 0; np < 2; np++) {
                uint32_t bd = base + 2 * TILE_B + (wn + np * 16 + lrow) * 80 + kbB;
                LDSM4(bh[np][0], bh[np][1], bh[np][2], bh[np][3], bd);
            }
#pragma unroll
            for (int mt = 0; mt < 4; mt++) {
                uint32_t ah[4], al[4];
                uint32_t ad = base + (wm + mt * 16 + lrow) * 80 + kbB;
                LDSM4(ah[0], ah[1], ah[2], ah[3], ad);
                LDSM4(al[0], al[1], al[2], al[3], ad + TILE_B);
#pragma unroll
                for (int nt = 0; nt < 4; nt++) {
                    int np = nt >> 1, s = nt & 1;
                    MMAH16816(c[mt][nt], ah, bh[np][s], bh[np][s + 2]);
                    MMAH16816(c[mt][nt], al, bh[np][s], bh[np][s + 2]);
                }
            }
        }
    }
    CP_WAIT0();

#pragma unroll
    for (int mt = 0; mt < 4; mt++) {
        int row = m0 + wm + mt * 16 + (lane >> 2);
#pragma unroll
        for (int nt = 0; nt < 4; nt++) {
            int col = n0 + wn + nt * 8 + (lane & 3) * 2;
            *(float2*)(C + (size_t)row * ldc + col)       = make_float2(c[mt][nt][0], c[mt][nt][1]);
            *(float2*)(C + (size_t)(row + 8) * ldc + col) = make_float2(c[mt][nt][2], c[mt][nt][3]);
        }
    }
}

// ================= gk / beta projection =================
__global__ void gkbeta2(const float* __restrict__ hs,
                        const float* __restrict__ Wgk, const float* __restrict__ Wb,
                        const float* __restrict__ bb,  const float* __restrict__ A_log,
                        const float* __restrict__ dt_bias,
                        float* __restrict__ gk, float* __restrict__ beta) {
    __shared__ float sh[8][HH];
    int w = threadIdx.x >> 5, lane = threadIdx.x & 31;
    int row = blockIdx.x * 8 + w;
    const float* hr = hs + (size_t)row * HH;
    for (int i = lane; i < HH; i += 32) sh[w][i] = hr[i];
    __syncwarp();
    if (lane < 24) {
        const float* W = (lane < 12) ? Wgk : Wb;
        int j = (lane < 12) ? lane : lane - 12;
        float acc = 0.f;
#pragma unroll 4
        for (int k = 0; k < HH; k++) acc += sh[w][k] * W[k * NHH + j];
        if (lane < 12) {
            acc += dt_bias[j];
            float sp = (acc > 20.f) ? acc : log1pf(expf(acc));
            gk[row * NHH + j] = -expf(A_log[j]) * sp;
        } else {
            acc += bb[j];
            beta[row * NHH + j] = 1.f / (1.f + expf(-acc));
        }
    }
}

// ================= conv + silu + l2norm (q & k, 4 units per 256-thr CTA) =================
__global__ void __launch_bounds__(256)
conv_silu_l2qk(const float* __restrict__ qkvg,
               const float* __restrict__ wq, const float* __restrict__ wk,
               float* __restrict__ outq, float* __restrict__ outk) {
    __shared__ float sred[8];
    int tid  = threadIdx.x;
    int unit = tid >> 6;
    int ch   = tid & 63;
    int idx  = blockIdx.x * 4 + unit;
    int which = idx & 1;
    idx >>= 1;
    int h  = idx % NHH;
    int bl = idx / NHH;
    int l  = bl % LL;
    int c  = h * DKK + ch;
    const float* in = qkvg + (which ? 768 : 0);
    const float* wr = (which ? wk : wq) + c * 4;
    float* out = which ? outk : outq;
    float acc = 0.f;
#pragma unroll
    for (int j = 0; j < 4; j++) {
        int tt = l - 3 + j;
        if (tt >= 0) acc += in[(size_t)(bl - l + tt) * NTOT + c] * wr[j];
    }
    float sv = acc / (1.f + expf(-acc));
    float ss = sv * sv;
#pragma unroll
    for (int off = 16; off; off >>= 1) ss += __shfl_xor_sync(0xffffffffu, ss, off);
    if ((tid & 31) == 0) sred[tid >> 5] = ss;
    __syncthreads();
    float n = sqrtf(sred[unit * 2] + sred[unit * 2 + 1]);
    out[(size_t)bl * KD + c] = sv / fmaxf(n, 1e-12f);
}

__global__ void conv_silu_v(const float* __restrict__ in, int istride,
                            const float* __restrict__ w, float* __restrict__ out, int total) {
    int gid = blockIdx.x * blockDim.x + threadIdx.x;
    if (gid >= total) return;
    int c  = gid % VD;
    int bl = gid / VD;
    int l  = bl % LL;
    const float* wr = w + c * 4;
    float acc = 0.f;
#pragma unroll
    for (int j = 0; j < 4; j++) {
        int tt = l - 3 + j;
        if (tt >= 0) acc += in[(size_t)(bl - l + tt) * istride + c] * wr[j];
    }
    out[gid] = acc / (1.f + expf(-acc));
}

// ================= recurrence v5: 128 thr, 16-step groups (best known) =================
#define TS 16
__global__ void __launch_bounds__(128)
recur5(const float* __restrict__ q, const float* __restrict__ k,
       const float* __restrict__ v, const float* __restrict__ gk,
       const float* __restrict__ beta, float* __restrict__ o) {
    int blk = blockIdx.x;
    int b  = blk / (NHH * 2);
    int h  = (blk >> 1) % NHH;
    int vh = blk & 1;
    int tid = threadIdx.x;
    int col  = tid >> 1;
    int half = tid & 1;

    __shared__ float ksh[2][TS][64];
    __shared__ float qsh[2][TS][64];
    __shared__ float vsh[2][TS][64];
    __shared__ float egsh[LL];
    __shared__ float bsh[LL];

    const float* qb = q + (size_t)b * LL * KD + h * DKK;
    const float* kb = k + (size_t)b * LL * KD + h * DKK;
    const float* vb = v + (size_t)b * LL * VD + h * DVV + vh * 64;
    const float* gb = gk + (size_t)b * LL * NHH + h;
    const float* be = beta + (size_t)b * LL * NHH + h;
    float* ob = o + (size_t)b * LL * VD + h * DVV + vh * 64;

    for (int i = tid; i < LL; i += 128) {
        egsh[i] = expf(gb[(size_t)i * NHH]);
        bsh[i]  = be[(size_t)i * NHH];
    }

    u64 S2[16];
#pragma unroll
    for (int i = 0; i < 16; i++) S2[i] = 0ull;

    const int ls = tid >> 6;
    const int lc = tid & 63;
#pragma unroll
    for (int i = 0; i < TS / 2; i++) {
        int s = i * 2 + ls;
        ksh[0][s][lc] = kb[(size_t)s * KD + lc];
        qsh[0][s][lc] = qb[(size_t)s * KD + lc];
        vsh[0][s][lc] = vb[(size_t)s * VD + lc];
    }
    __syncthreads();

    const int NG = LL / TS;
    for (int g = 0; g < NG; g++) {
        const int buf = g & 1;
        float rk[TS / 2], rq[TS / 2], rv[TS / 2];
        const bool more = (g + 1) < NG;
        if (more) {
            int t0 = (g + 1) * TS;
#pragma unroll
            for (int i = 0; i < TS / 2; i++) {
                int s = i * 2 + ls;
                rk[i] = kb[(size_t)(t0 + s) * KD + lc];
                rq[i] = qb[(size_t)(t0 + s) * KD + lc];
                rv[i] = vb[(size_t)(t0 + s) * VD + lc];
            }
        }
#pragma unroll
        for (int s = 0; s < TS; s++) {
            int t = g * TS + s;
            float eg = egsh[t], bt = bsh[t];
            float vv = vsh[buf][s][col];
            const u64* kh2 = (const u64*)&ksh[buf][s][half * 32];
            const u64* qh2 = (const u64*)&qsh[buf][s][half * 32];

            u64 eg2; DUP2(eg2, __float_as_uint(eg));
            u64 p0 = 0ull, p1 = 0ull, p2 = 0ull, p3 = 0ull;
#pragma unroll
            for (int j = 0; j < 16; j += 4) {
                MUL2(S2[j],     S2[j],     eg2);
                MUL2(S2[j + 1], S2[j + 1], eg2);
                MUL2(S2[j + 2], S2[j + 2], eg2);
                MUL2(S2[j + 3], S2[j + 3], eg2);
                FMA2(p0, kh2[j],     S2[j]);
                FMA2(p1, kh2[j + 1], S2[j + 1]);
                FMA2(p2, kh2[j + 2], S2[j + 2]);
                FMA2(p3, kh2[j + 3], S2[j + 3]);
            }
            u32 a0, a1, a2, a3, a4, a5, a6, a7;
            UNPK2(a0, a1, p0); UNPK2(a2, a3, p1);
            UNPK2(a4, a5, p2); UNPK2(a6, a7, p3);
            float pred = ((__uint_as_float(a0) + __uint_as_float(a1)) +
                          (__uint_as_float(a2) + __uint_as_float(a3))) +
                         ((__uint_as_float(a4) + __uint_as_float(a5)) +
                          (__uint_as_float(a6) + __uint_as_float(a7)));
            pred += __shfl_xor_sync(0xffffffffu, pred, 1);
            float delta = bt * (vv - pred);

            u64 d2; DUP2(d2, __float_as_uint(delta));
            u64 o0 = 0ull, o1 = 0ull, o2 = 0ull, o3 = 0ull;
#pragma unroll
            for (int j = 0; j < 16; j += 4) {
                FMA2(S2[j],     kh2[j],     d2);
                FMA2(S2[j + 1], kh2[j + 1], d2);
                FMA2(S2[j + 2], kh2[j + 2], d2);
                FMA2(S2[j + 3], kh2[j + 3], d2);
                FMA2(o0, qh2[j],     S2[j]);
                FMA2(o1, qh2[j + 1], S2[j + 1]);
                FMA2(o2, qh2[j + 2], S2[j + 2]);
                FMA2(o3, qh2[j + 3], S2[j + 3]);
            }
            UNPK2(a0, a1, o0); UNPK2(a2, a3, o1);
            UNPK2(a4, a5, o2); UNPK2(a6, a7, o3);
            float out = ((__uint_as_float(a0) + __uint_as_float(a1)) +
                         (__uint_as_float(a2) + __uint_as_float(a3))) +
                        ((__uint_as_float(a4) + __uint_as_float(a5)) +
                         (__uint_as_float(a6) + __uint_as_float(a7)));
            out += __shfl_xor_sync(0xffffffffu, out, 1);
            if (half == 0) ob[(size_t)t * VD + col] = out;
        }
        if (more) {
#pragma unroll
            for (int i = 0; i < TS / 2; i++) {
                int s = i * 2 + ls;
                ksh[buf ^ 1][s][lc] = rk[i];
                qsh[buf ^ 1][s][lc] = rq[i];
                vsh[buf ^ 1][s][lc] = rv[i];
            }
        }
        __syncthreads();
    }
}

// ================= rmsnorm * gnorm_w * silu(g) -> fp16 hi/lo =================
__global__ void rmsgate_kernel(const float* __restrict__ o, const float* __restrict__ g,
                               const float* __restrict__ gw,
                               __half* __restrict__ oh, __half* __restrict__ ol) {
    int bl = blockIdx.x / NHH, h = blockIdx.x % NHH;
    size_t obase = (size_t)blockIdx.x * DVV;
    size_t gbase = (size_t)bl * NTOT + h * DVV;
    int tid = threadIdx.x;
    float val = o[obase + tid];
    float ss = val * val;
#pragma unroll
    for (int off = 16; off; off >>= 1) ss += __shfl_xor_sync(0xffffffffu, ss, off);
    __shared__ float sr[4];
    if ((tid & 31) == 0) sr[tid >> 5] = ss;
    __syncthreads();
    float tot = sr[0] + sr[1] + sr[2] + sr[3];
    float r = rsqrtf(tot / DVV + 1e-5f);
    float gv = g[gbase + tid];
    float sgt = gv / (1.f + expf(-gv));
    float res = val * r * gw[tid] * sgt;
    __half hi = __float2half_rn(res);
    oh[obase + tid] = hi;
    ol[obase + tid] = __float2half_rn(res - __half2float(hi));
}

// ================= launch =================
extern "C" void kernel_launch(void* const* d_in, const int* in_sizes, int n_in,
                              void* d_out, int out_size) {
    const float *hs = 0, *Wq = 0, *Wk = 0, *Wv = 0, *Wg = 0, *Wgk = 0, *Wb = 0,
                *bbp = 0, *convq = 0, *convk = 0, *convv = 0, *Alog = 0,
                *dtb = 0, *gnw = 0, *Wo = 0;
    int c786 = 0, c1572 = 0, c12288 = 0, c12 = 0, c3072 = 0;
    for (int i = 0; i < n_in; i++) {
        const float* p = (const float*)d_in[i];
        switch (in_sizes[i]) {
            case 8388608: hs = p; break;
            case 786432:  if (c786++ == 0) Wq = p; else Wk = p; break;
            case 1572864: { int j = c1572++; if (j == 0) Wv = p; else if (j == 1) Wg = p; else Wo = p; } break;
            case 12288:   if (c12288++ == 0) Wgk = p; else Wb = p; break;
            case 12:      { int j = c12++; if (j == 0) bbp = p; else if (j == 1) Alog = p; else dtb = p; } break;
            case 3072:    if (c3072++ == 0) convq = p; else convk = p; break;
            case 6144:    convv = p; break;
            case 128:     gnw = p; break;
            default: break;
        }
    }

    float *qkvg, *bQc, *bKc, *bVc, *bO, *bgk, *bbe;
    __half *hsh, *hsl, *wth, *woth, *oh, *ol;
    cudaGetSymbolAddress((void**)&qkvg, g_qkvg);
    cudaGetSymbolAddress((void**)&hsh,  g_hsh);
    cudaGetSymbolAddress((void**)&hsl,  g_hsl);
    cudaGetSymbolAddress((void**)&wth,  g_wth);
    cudaGetSymbolAddress((void**)&woth, g_woth);
    cudaGetSymbolAddress((void**)&oh,   g_oh);
    cudaGetSymbolAddress((void**)&ol,   g_ol);
    cudaGetSymbolAddress((void**)&bQc,  g_bufQc);
    cudaGetSymbolAddress((void**)&bKc,  g_bufKc);
    cudaGetSymbolAddress((void**)&bVc,  g_bufVc);
    cudaGetSymbolAddress((void**)&bO,   g_bufO);
    cudaGetSymbolAddress((void**)&bgk,  g_gk);
    cudaGetSymbolAddress((void**)&bbe,  g_beta);

    cudaFuncSetAttribute(gemm_mma, cudaFuncAttributeMaxDynamicSharedMemorySize, SMEM_GEMM);

    split_kernel<<<(BL * HH + 255) / 256, 256>>>(hs, hsh, hsl, BL * HH);
    transp_all<<<6144, dim3(32, 8)>>>(Wq, Wk, Wv, Wg, Wo, wth, woth);
    gkbeta2<<<BL / 8, 256>>>(hs, Wgk, Wb, bbp, Alog, dtb, bgk, bbe);

    gemm_mma<<<dim3(NTOT / 128, BL / 128), 256, SMEM_GEMM>>>(hsh, hsl, wth, qkvg, HH, NTOT);

    conv_silu_l2qk<<<BL * NHH * 2 / 4, 256>>>(qkvg, convq, convk, bQc, bKc);
    int totv = BL * VD;
    conv_silu_v<<<(totv + 255) / 256, 256>>>(qkvg + 1536, NTOT, convv, bVc, totv);

    recur5<<<BB * NHH * 2, 128>>>(bQc, bKc, bVc, bgk, bbe, bO);

    rmsgate_kernel<<<BL * NHH, 128>>>(bO, qkvg + 3072, gnw, oh, ol);

    gemm_mma<<<dim3(HH / 128, BL / 128), 256, SMEM_GEMM>>>(oh, ol, woth, (float*)d_out, VD, HH);
}